// round 7
// baseline (speedup 1.0000x reference)
#include <cuda_runtime.h>

#define BATCH 8
#define INPUT_SIZE 8192
#define HIDDEN_SIZE 8192
#define OUTPUT_SIZE 2048
#define KDIM 16384

typedef unsigned long long u64;

// Intermediate hidden activations (8 x 8192 fp32 = 256 KB).
__device__ float g_hidden[BATCH * HIDDEN_SIZE];
// Partial sums for the K-split h2o GEMV: [split][batch][out]
__device__ float g_part[2][BATCH][OUTPUT_SIZE];

// ---------------------------------------------------------------------------
// cp.async helpers (16B variant)
// ---------------------------------------------------------------------------
__device__ __forceinline__ void cp_async16(void* smem_dst, const void* gmem_src) {
    unsigned s = (unsigned)__cvta_generic_to_shared(smem_dst);
    asm volatile("cp.async.cg.shared.global [%0], [%1], 16;\n" :: "r"(s), "l"(gmem_src));
}
__device__ __forceinline__ void cp_commit()  { asm volatile("cp.async.commit_group;\n"); }
__device__ __forceinline__ void cp_wait1()   { asm volatile("cp.async.wait_group 1;\n"); }
__device__ __forceinline__ void cp_wait0()   { asm volatile("cp.async.wait_group 0;\n"); }

// Pack two f32 into a register pair (coalesced by ptxas into existing pair).
__device__ __forceinline__ u64 pk2(float lo, float hi) {
    u64 r; asm("mov.b64 %0, {%1, %2};" : "=l"(r) : "f"(lo), "f"(hi)); return r;
}
// Packed dual-FMA (NON-volatile: pure, reorderable): d += a*b elementwise.
__device__ __forceinline__ void fma2(u64& d, u64 a, u64 b) {
    asm("fma.rn.f32x2 %0, %1, %2, %0;" : "+l"(d) : "l"(a), "l"(b));
}
__device__ __forceinline__ float pair_sum(u64 v) {
    return __uint_as_float((unsigned)v) + __uint_as_float((unsigned)(v >> 32));
}

#define TK  512
#define TK4 (TK / 4)    // 128 float4 per batch per chunk

// ===========================================================================
// Kernel 1: hidden[b,h] = tanh( x[b,:]·W[h,0:8192] + h0[b,:]·W[h,8192:] + b1[h] )
// 256 threads (8 warps), 4 rows/warp -> 32 rows/block, grid = 256. Full K per
// block, cp.async double-buffered staging (exact R2 structure); f32x2 math.
// ===========================================================================
#define R1 4
#define ROWS_PER_BLOCK_1 (R1 * 8)   // 32

__global__ __launch_bounds__(256, 2)
void rnn_i2h_kernel(const float* __restrict__ x,
                    const float* __restrict__ h0,
                    const float* __restrict__ W,      // [HIDDEN_SIZE, KDIM]
                    const float* __restrict__ bias)
{
    __shared__ float4 s_in[2][BATCH][TK4];   // 2 x 16 KB

    const int tid  = threadIdx.x;
    const int lane = tid & 31;
    const int warp = tid >> 5;
    const int row0 = blockIdx.x * ROWS_PER_BLOCK_1 + warp * R1;

    const int NCHUNK = KDIM / TK;          // 32
    const int XCHUNK = INPUT_SIZE / TK;    // 16

    u64 acc[R1][BATCH];
    #pragma unroll
    for (int r = 0; r < R1; r++)
        #pragma unroll
        for (int b = 0; b < BATCH; b++)
            acc[r][b] = 0ull;

    auto stage = [&](int c, int buf) {
        const float* src = (c < XCHUNK) ? (x + c * TK)
                                        : (h0 + (c - XCHUNK) * TK);
        #pragma unroll
        for (int t = 0; t < 4; ++t) {
            int f  = tid + t * 256;
            int b  = f >> 7;            // / TK4 (=128)
            int k4 = f & (TK4 - 1);
            cp_async16(&s_in[buf][b][k4],
                       (const float4*)(src + (size_t)b * INPUT_SIZE) + k4);
        }
        cp_commit();
    };

    stage(0, 0);

    const float* Wr0 = W + (size_t)(row0 + 0) * KDIM;
    const float* Wr1 = W + (size_t)(row0 + 1) * KDIM;
    const float* Wr2 = W + (size_t)(row0 + 2) * KDIM;
    const float* Wr3 = W + (size_t)(row0 + 3) * KDIM;

    for (int c = 0; c < NCHUNK; ++c) {
        const int buf = c & 1;
        __syncthreads();                     // buffer (c+1)&1 free now
        if (c + 1 < NCHUNK) { stage(c + 1, buf ^ 1); cp_wait1(); }
        else                { cp_wait0(); }
        __syncthreads();                     // chunk c visible

        const float* Wc0 = Wr0 + (size_t)c * TK;
        const float* Wc1 = Wr1 + (size_t)c * TK;
        const float* Wc2 = Wr2 + (size_t)c * TK;
        const float* Wc3 = Wr3 + (size_t)c * TK;

        #pragma unroll
        for (int i = 0; i < TK4 / 32; ++i) {          // 4 strips
            const int k4 = i * 32 + lane;
            float4 w0 = __ldcs((const float4*)Wc0 + k4);
            float4 w1 = __ldcs((const float4*)Wc1 + k4);
            float4 w2 = __ldcs((const float4*)Wc2 + k4);
            float4 w3 = __ldcs((const float4*)Wc3 + k4);

            u64 wa0 = pk2(w0.x, w0.y), wb0 = pk2(w0.z, w0.w);
            u64 wa1 = pk2(w1.x, w1.y), wb1 = pk2(w1.z, w1.w);
            u64 wa2 = pk2(w2.x, w2.y), wb2 = pk2(w2.z, w2.w);
            u64 wa3 = pk2(w3.x, w3.y), wb3 = pk2(w3.z, w3.w);

            #pragma unroll
            for (int b = 0; b < BATCH; b++) {
                float4 v = s_in[buf][b][k4];
                u64 va = pk2(v.x, v.y), vb = pk2(v.z, v.w);
                fma2(acc[0][b], wa0, va);
                fma2(acc[0][b], wb0, vb);
                fma2(acc[1][b], wa1, va);
                fma2(acc[1][b], wb1, vb);
                fma2(acc[2][b], wa2, va);
                fma2(acc[2][b], wb2, vb);
                fma2(acc[3][b], wa3, va);
                fma2(acc[3][b], wb3, vb);
            }
        }
    }

    // warp butterfly reduction
    #pragma unroll
    for (int r = 0; r < R1; r++) {
        #pragma unroll
        for (int b = 0; b < BATCH; b++) {
            float s = pair_sum(acc[r][b]);
            #pragma unroll
            for (int off = 16; off > 0; off >>= 1)
                s += __shfl_xor_sync(0xffffffffu, s, off);
            if (lane == b) {
                const int row = row0 + r;
                g_hidden[b * HIDDEN_SIZE + row] = tanhf(s + __ldg(bias + row));
            }
        }
    }
}

// ===========================================================================
// Kernel 2: K-split GEMV. part[s][b,o] = hidden[b, s*4096:(s+1)*4096]·W2[o,...]
// 256 threads, 2 rows/warp -> 16 rows/block, grid = 128 tiles x 2 splits.
// ===========================================================================
#define R2 2
#define ROWS_PER_BLOCK_2 (R2 * 8)   // 16
#define KSPLIT 2
#define KHALF (HIDDEN_SIZE / KSPLIT)   // 4096

__global__ __launch_bounds__(256, 2)
void rnn_h2o_kernel(const float* __restrict__ W2)   // [OUTPUT_SIZE, HIDDEN_SIZE]
{
    __shared__ float4 s_in[2][BATCH][TK4];   // 2 x 16 KB

    const int tid  = threadIdx.x;
    const int lane = tid & 31;
    const int warp = tid >> 5;
    const int tile = blockIdx.x & 127;
    const int half = blockIdx.x >> 7;
    const int row0 = tile * ROWS_PER_BLOCK_2 + warp * R2;
    const int kbase = half * KHALF;

    const int NCHUNK = KHALF / TK;   // 8

    u64 acc[R2][BATCH];
    #pragma unroll
    for (int r = 0; r < R2; r++)
        #pragma unroll
        for (int b = 0; b < BATCH; b++)
            acc[r][b] = 0ull;

    auto stage = [&](int c, int buf) {
        const float* src = g_hidden + kbase + c * TK;
        #pragma unroll
        for (int t = 0; t < 4; ++t) {
            int f  = tid + t * 256;
            int b  = f >> 7;
            int k4 = f & (TK4 - 1);
            cp_async16(&s_in[buf][b][k4],
                       (const float4*)(src + (size_t)b * HIDDEN_SIZE) + k4);
        }
        cp_commit();
    };

    stage(0, 0);

    const float* W0 = W2 + (size_t)(row0 + 0) * HIDDEN_SIZE + kbase;
    const float* W1 = W2 + (size_t)(row0 + 1) * HIDDEN_SIZE + kbase;

    for (int c = 0; c < NCHUNK; ++c) {
        const int buf = c & 1;
        __syncthreads();
        if (c + 1 < NCHUNK) { stage(c + 1, buf ^ 1); cp_wait1(); }
        else                { cp_wait0(); }
        __syncthreads();

        const float* Wc0 = W0 + (size_t)c * TK;
        const float* Wc1 = W1 + (size_t)c * TK;

        #pragma unroll
        for (int i = 0; i < TK4 / 32; ++i) {
            const int k4 = i * 32 + lane;
            float4 w0 = __ldcs((const float4*)Wc0 + k4);
            float4 w1 = __ldcs((const float4*)Wc1 + k4);
            u64 wa0 = pk2(w0.x, w0.y), wb0 = pk2(w0.z, w0.w);
            u64 wa1 = pk2(w1.x, w1.y), wb1 = pk2(w1.z, w1.w);

            #pragma unroll
            for (int b = 0; b < BATCH; b++) {
                float4 v = s_in[buf][b][k4];
                u64 va = pk2(v.x, v.y), vb = pk2(v.z, v.w);
                fma2(acc[0][b], wa0, va);
                fma2(acc[0][b], wb0, vb);
                fma2(acc[1][b], wa1, va);
                fma2(acc[1][b], wb1, vb);
            }
        }
    }

    #pragma unroll
    for (int r = 0; r < R2; r++) {
        #pragma unroll
        for (int b = 0; b < BATCH; b++) {
            float s = pair_sum(acc[r][b]);
            #pragma unroll
            for (int off = 16; off > 0; off >>= 1)
                s += __shfl_xor_sync(0xffffffffu, s, off);
            if (lane == b)
                g_part[half][b][row0 + r] = s;
        }
    }
}

// ===========================================================================
// Kernel 3: out[b,o] = part[0][b,o] + part[1][b,o] + bias2[o]
// ===========================================================================
__global__ void rnn_reduce_kernel(const float* __restrict__ bias2,
                                  float* __restrict__ out)
{
    int idx = blockIdx.x * blockDim.x + threadIdx.x;   // 16384
    int b = idx >> 11;
    int o = idx & (OUTPUT_SIZE - 1);
    out[idx] = g_part[0][b][o] + g_part[1][b][o] + __ldg(bias2 + o);
}

// ---------------------------------------------------------------------------
// Inputs: x, initial_hidden, i2h_weight, i2h_bias, h2o_weight, h2o_bias
// ---------------------------------------------------------------------------
extern "C" void kernel_launch(void* const* d_in, const int* in_sizes, int n_in,
                              void* d_out, int out_size) {
    const float* x  = (const float*)d_in[0];
    const float* h0 = (const float*)d_in[1];
    const float* W1 = (const float*)d_in[2];
    const float* b1 = (const float*)d_in[3];
    const float* W2 = (const float*)d_in[4];
    const float* b2 = (const float*)d_in[5];
    float* out      = (float*)d_out;

    rnn_i2h_kernel<<<HIDDEN_SIZE / ROWS_PER_BLOCK_1, 256>>>(x, h0, W1, b1);
    rnn_h2o_kernel<<<(OUTPUT_SIZE / ROWS_PER_BLOCK_2) * KSPLIT, 256>>>(W2);
    rnn_reduce_kernel<<<(BATCH * OUTPUT_SIZE) / 256, 256>>>(b2, out);
}